// round 13
// baseline (speedup 1.0000x reference)
#include <cuda_runtime.h>
#include <math.h>

#define DIM 512
#define MARGIN 1.0f
#define RULE_WEIGHT 0.5f

#define MAX_B 1024

// Scratch (allocation-free). g_dposm doubles as flag+value: 0 = not ready,
// MARGIN + d >= 1 when published. Zero at load; last block re-zeroes each
// call so graph replays are deterministic.
__device__ float g_dposm[MAX_B];
__device__ float g_loss = 0.f;
__device__ float g_rule_sum = 0.f;
__device__ unsigned int g_ticket = 0;

__device__ __forceinline__ float warp_red(float v) {
#pragma unroll
    for (int o = 16; o; o >>= 1) v += __shfl_xor_sync(0xffffffffu, v, o);
    return v;
}

// GPU-scope relaxed ld/st — plain strong-GPU LDG/STG, NOT the SYS-scope ops
// that `volatile` generates (R12's diagnosed cost). No membar, no CCTL.
__device__ __forceinline__ float ld_relaxed_gpu(const float* p) {
    float v;
    asm volatile("ld.relaxed.gpu.global.f32 %0, [%1];" : "=f"(v) : "l"(p) : "memory");
    return v;
}
__device__ __forceinline__ void st_relaxed_gpu(float* p, float v) {
    asm volatile("st.relaxed.gpu.global.f32 [%0], %1;" :: "l"(p), "f"(v) : "memory");
}

// acq_rel ticket: release orders this thread's prior global ops (its g_loss
// atomicAdd) before the increment; winner's acquire orders subsequent reads.
__device__ __forceinline__ unsigned int ticket_acq_rel(unsigned int* p) {
    unsigned int old;
    asm volatile("atom.acq_rel.gpu.global.add.u32 %0, [%1], 1;"
                 : "=r"(old) : "l"(p) : "memory");
    return old;
}

// TransH distance via expanded norm (R11, measured win): single streaming
// pass over w and re; only hd[4] + 4 scalar accumulators live.
//   u = hd + re;  ||u - c*w||^2 = uu - 2c*uw + c^2*ww,  c = (hd.w)/ww
__device__ __forceinline__ float dist_lowreg(
    const float4 hd[4],
    const float* __restrict__ rel, const float* __restrict__ nv,
    int r, int lane)
{
    const float4* w4  = reinterpret_cast<const float4*>(nv  + (size_t)r * DIM);
    const float4* re4 = reinterpret_cast<const float4*>(rel + (size_t)r * DIM);
    float ww = 0.f, dw = 0.f, uu = 0.f, uw = 0.f;
#pragma unroll
    for (int i = 0; i < 4; i++) {
        float4 w  = w4[lane + 32 * i];
        float4 re = re4[lane + 32 * i];
        float ux = hd[i].x + re.x, uy = hd[i].y + re.y;
        float uz = hd[i].z + re.z, uq = hd[i].w + re.w;
        ww += w.x * w.x + w.y * w.y + w.z * w.z + w.w * w.w;
        dw += hd[i].x * w.x + hd[i].y * w.y + hd[i].z * w.z + hd[i].w * w.w;
        uu += ux * ux + uy * uy + uz * uz + uq * uq;
        uw += ux * w.x + uy * w.y + uz * w.z + uq * w.w;
    }
    ww = warp_red(ww);
    dw = warp_red(dw);
    uu = warp_red(uu);
    uw = warp_red(uw);
    float c = dw / ww;
    float ss = uu - 2.f * c * uw + c * c * ww;
    return sqrtf(fmaxf(ss, 0.f));
}

// Single kernel. Pos warps (blocks 0..B/8-1, all wave-1 resident) publish
// MARGIN+d via relaxed store. Neg blocks: 8 warps = 8 consecutive negs that
// all pair with ONE pos index -> one poller per block (tid 0), smem
// broadcast, per-warp relu, one global atomic per block. Ticketed last
// block combines two scalars and resets state.
__global__ void __launch_bounds__(256)
fused_all(const int* __restrict__ pos, const int* __restrict__ neg,
          const int* __restrict__ rr1, const int* __restrict__ rr2,
          const float* __restrict__ rconf,
          const float* __restrict__ ent, const float* __restrict__ rel,
          const float* __restrict__ nv,
          float* __restrict__ out,
          int B, int NEG, int NR)
{
    int tid  = threadIdx.x;
    int gw   = (blockIdx.x * blockDim.x + tid) >> 5;
    int lane = tid & 31;
    int ratio = NEG / B;
    int wpb   = blockDim.x >> 5;              // warps per block (8)
    bool shared_kp = (ratio == wpb);          // all neg warps in block share kp

    __shared__ float s_loss;
    __shared__ float s_pm;
    if (tid == 0) { s_loss = 0.f; s_pm = 0.f; }
    __syncthreads();

    bool in_range = (gw < B + NEG);
    bool is_pos   = (gw < B);
    float d = 0.f;
    int kneg = gw - B;

    if (in_range) {
        int h, r, t;
        if (is_pos) {
            h = pos[3 * gw]; r = pos[3 * gw + 1]; t = pos[3 * gw + 2];
        } else {
            h = neg[3 * kneg]; r = neg[3 * kneg + 1]; t = neg[3 * kneg + 2];
        }

        const float4* he4 = reinterpret_cast<const float4*>(ent + (size_t)h * DIM);
        const float4* te4 = reinterpret_cast<const float4*>(ent + (size_t)t * DIM);
        float4 hd[4];
#pragma unroll
        for (int i = 0; i < 4; i++) {
            float4 a = he4[lane + 32 * i];
            float4 b = te4[lane + 32 * i];
            hd[i].x = a.x - b.x; hd[i].y = a.y - b.y;
            hd[i].z = a.z - b.z; hd[i].w = a.w - b.w;
        }

        d = dist_lowreg(hd, rel, nv, r, lane);

        if (is_pos) {
            // Only rules with rule_r1[j] == r contribute (mask exact-zeros rest).
            float racc = 0.f;
            for (int j = 0; j < NR; j++) {
                if (rr1[j] == r)
                    racc += rconf[j] * dist_lowreg(hd, rel, nv, rr2[j], lane);
            }
            if (lane == 0) {
                st_relaxed_gpu(&g_dposm[gw], MARGIN + d);       // publish (>=1)
                if (racc != 0.f) atomicAdd(&g_rule_sum, racc);  // ~40 warps
            }
        }
    }

    // ---- Pairing (neg blocks only) ----
    if (in_range && !is_pos) {
        if (shared_kp) {
            __syncthreads();                        // all 8 neg dists ready
            if (tid == 0) {
                int kp = kneg / ratio;              // same for whole block
                float pm;
                do { pm = ld_relaxed_gpu(&g_dposm[kp]); } while (pm == 0.f);
                s_pm = pm;
            }
            __syncthreads();
            float v = s_pm - d;                     // MARGIN + d_pos - d_neg
            if (lane == 0 && v > 0.f) atomicAdd(&s_loss, v);
        } else {
            // generic fallback: each warp polls its own pos word
            float pm;
            if (lane == 0) {
                int kp = kneg / ratio;
                do { pm = ld_relaxed_gpu(&g_dposm[kp]); } while (pm == 0.f);
            }
            pm = __shfl_sync(0xffffffffu, pm, 0);
            float v = pm - d;
            if (lane == 0 && v > 0.f) atomicAdd(&s_loss, v);
        }
    } else if (shared_kp) {
        // pos / out-of-range blocks must match the neg blocks' barrier count
        // only within their OWN block — barriers are block-scoped, and every
        // block takes a consistent path (block is purely pos or purely neg
        // when B % wpb == 0), so no divergence hazard; pos blocks skip.
    }

    // ---- One global atomic per block, then ticket ----
    __syncthreads();
    __shared__ unsigned int s_last;
    if (tid == 0) {
        if (s_loss != 0.f) atomicAdd(&g_loss, s_loss);
        s_last = (ticket_acq_rel(&g_ticket) == gridDim.x - 1) ? 1u : 0u;
    }
    __syncthreads();
    if (!s_last) return;

    // ---- Trivial tail: combine + reset (all blocks ticketed => done) ----
    for (int i = tid; i < B; i += blockDim.x) g_dposm[i] = 0.f;  // re-arm flags
    if (tid == 0) {
        float bl = g_loss;
        float rs = g_rule_sum;
        out[0] = bl / (float)NEG + RULE_WEIGHT * rs;
        g_loss = 0.f;
        g_rule_sum = 0.f;
        g_ticket = 0;
    }
}

extern "C" void kernel_launch(void* const* d_in, const int* in_sizes, int n_in,
                              void* d_out, int out_size)
{
    const int*   pos   = (const int*)d_in[0];
    const int*   neg   = (const int*)d_in[1];
    const int*   rr1   = (const int*)d_in[2];
    const int*   rr2   = (const int*)d_in[3];
    const float* rconf = (const float*)d_in[4];
    const float* ent   = (const float*)d_in[5];
    const float* rel   = (const float*)d_in[6];
    const float* nv    = (const float*)d_in[7];

    int B   = in_sizes[0] / 3;
    int NEG = in_sizes[1] / 3;
    int NR  = in_sizes[2];

    int totalWarps = B + NEG;
    int blocks = (totalWarps * 32 + 255) / 256;

    fused_all<<<blocks, 256>>>(pos, neg, rr1, rr2, rconf, ent, rel, nv,
                               (float*)d_out, B, NEG, NR);
}